// round 4
// baseline (speedup 1.0000x reference)
#include <cuda_runtime.h>

// FAC (per-pixel dynamic 3x3 filter) + LeakyReLU(0.2)
// feature: [N=8, C=64, H=128, W=128] f32
// filters: [N, C*9, H, W] f32, tap index = kh*3+kw minor within channel-major C
// out[n,c,h,w] = leaky( sum_{kh,kw} filters[n, c*9+kh*3+kw, h, w] *
//                                   feat_pad[n, c, h+kh-1, w+kw-1] )
//
// HBM-bound: ~369 MB total traffic. Vectorized float4 along W: each thread
// produces 4 outputs; 9 coalesced LDG.128 filter loads + 3 rows of feature
// (LDG.128 + 2 halo scalars) + 1 STG.128.

#define HW 16384      // 128*128
#define W  128
#define H  128

__global__ __launch_bounds__(256, 8)
void fac_leaky_kernel(const float* __restrict__ feat,
                      const float* __restrict__ filt,
                      float* __restrict__ out)
{
    // vec index over N*C*H*(W/4) = 2,097,152
    int idx = blockIdx.x * blockDim.x + threadIdx.x;

    int wv = idx & 31;              // W/4 groups
    int h  = (idx >> 5) & 127;
    int nc = idx >> 12;             // n*64 + c
    int w0 = wv << 2;

    const float* fb = feat + (size_t)nc * HW;                       // feature plane
    const float* pb = filt + (size_t)nc * 9 * HW + h * W + w0;      // filter taps

    float acc0 = 0.f, acc1 = 0.f, acc2 = 0.f, acc3 = 0.f;

    #pragma unroll
    for (int kh = 0; kh < 3; ++kh) {
        int hh = h + kh - 1;
        float f0, f1, f2, f3, f4, f5;   // feat row window [w0-1 .. w0+4]
        if (hh >= 0 && hh < H) {
            const float* row = fb + hh * W;
            float4 mid = *reinterpret_cast<const float4*>(row + w0);
            f0 = (w0 > 0)      ? __ldg(row + w0 - 1) : 0.f;
            f1 = mid.x; f2 = mid.y; f3 = mid.z; f4 = mid.w;
            f5 = (w0 + 4 < W)  ? __ldg(row + w0 + 4) : 0.f;
        } else {
            f0 = f1 = f2 = f3 = f4 = f5 = 0.f;
        }

        // kw = 0 : tap kh*3+0 multiplies window offset [0..3]
        {
            float4 wv4 = *reinterpret_cast<const float4*>(pb + (kh * 3 + 0) * HW);
            acc0 = fmaf(wv4.x, f0, acc0);
            acc1 = fmaf(wv4.y, f1, acc1);
            acc2 = fmaf(wv4.z, f2, acc2);
            acc3 = fmaf(wv4.w, f3, acc3);
        }
        // kw = 1 : offset [1..4]
        {
            float4 wv4 = *reinterpret_cast<const float4*>(pb + (kh * 3 + 1) * HW);
            acc0 = fmaf(wv4.x, f1, acc0);
            acc1 = fmaf(wv4.y, f2, acc1);
            acc2 = fmaf(wv4.z, f3, acc2);
            acc3 = fmaf(wv4.w, f4, acc3);
        }
        // kw = 2 : offset [2..5]
        {
            float4 wv4 = *reinterpret_cast<const float4*>(pb + (kh * 3 + 2) * HW);
            acc0 = fmaf(wv4.x, f2, acc0);
            acc1 = fmaf(wv4.y, f3, acc1);
            acc2 = fmaf(wv4.z, f4, acc2);
            acc3 = fmaf(wv4.w, f5, acc3);
        }
    }

    float4 o;
    o.x = acc0 >= 0.f ? acc0 : 0.2f * acc0;
    o.y = acc1 >= 0.f ? acc1 : 0.2f * acc1;
    o.z = acc2 >= 0.f ? acc2 : 0.2f * acc2;
    o.w = acc3 >= 0.f ? acc3 : 0.2f * acc3;

    *reinterpret_cast<float4*>(out + (size_t)nc * HW + h * W + w0) = o;
}

extern "C" void kernel_launch(void* const* d_in, const int* in_sizes, int n_in,
                              void* d_out, int out_size)
{
    const float* feature = (const float*)d_in[0];   // 8*64*128*128
    const float* filters = (const float*)d_in[1];   // 8*576*128*128
    float* out = (float*)d_out;

    // total float4 outputs: 8*64*128*128/4 = 2,097,152
    const int total_vec = 8 * 64 * 128 * (128 / 4);
    const int threads = 256;
    const int blocks = total_vec / threads;         // 8192

    fac_leaky_kernel<<<blocks, threads>>>(feature, filters, out);
}

// round 5
// speedup vs baseline: 1.1922x; 1.1922x over previous
#include <cuda_runtime.h>

// FAC (per-pixel dynamic 3x3 filter) + LeakyReLU(0.2)
// feature: [N=8, C=64, H=128, W=128] f32
// filters: [N, C*9, H, W] f32, tap index = kh*3+kw minor within channel-major C
//
// HBM-bound at the ~369 MB traffic floor. R5 changes vs R4:
//  - warp covers a full row (lane == wv): w-halo via __shfl instead of 6
//    predicated scalar LDGs per thread (fewer L1 wavefronts, no divergence)
//  - filters streamed with __ldcs (read-once, evict-first: don't thrash L2)
//  - output stored with __stcs (no L2 write-allocate pollution)
// Goal: push dram__cycles_active 85.9% -> ~90%.

#define HW 16384      // 128*128
#define W  128
#define H  128

__device__ __forceinline__ float4 ldcs4(const float* p) {
    float4 v;
    asm volatile("ld.global.cs.v4.f32 {%0,%1,%2,%3}, [%4];"
                 : "=f"(v.x), "=f"(v.y), "=f"(v.z), "=f"(v.w)
                 : "l"(p));
    return v;
}

__device__ __forceinline__ void stcs4(float* p, float4 v) {
    asm volatile("st.global.cs.v4.f32 [%0], {%1,%2,%3,%4};"
                 :: "l"(p), "f"(v.x), "f"(v.y), "f"(v.z), "f"(v.w)
                 : "memory");
}

__global__ __launch_bounds__(256, 8)
void fac_leaky_kernel(const float* __restrict__ feat,
                      const float* __restrict__ filt,
                      float* __restrict__ out)
{
    // vec index over N*C*H*(W/4) = 2,097,152; lane == wv (warp spans one row)
    int idx = blockIdx.x * blockDim.x + threadIdx.x;

    int lane = idx & 31;            // == wv, W/4 groups
    int h  = (idx >> 5) & 127;
    int nc = idx >> 12;             // n*64 + c
    int w0 = lane << 2;

    const float* fb = feat + (size_t)nc * HW;                       // feature plane
    const float* pb = filt + (size_t)nc * 9 * HW + h * W + w0;      // filter taps

    float acc0 = 0.f, acc1 = 0.f, acc2 = 0.f, acc3 = 0.f;

    #pragma unroll
    for (int kh = 0; kh < 3; ++kh) {
        int hh = h + kh - 1;

        float4 mid;
        if (hh >= 0 && hh < H) {
            mid = *reinterpret_cast<const float4*>(fb + hh * W + w0);
        } else {
            mid = make_float4(0.f, 0.f, 0.f, 0.f);
        }
        // halo from neighbor lanes; lane 0 / lane 31 are the zero-pad edges
        float f0 = __shfl_up_sync(0xffffffffu, mid.w, 1);
        float f5 = __shfl_down_sync(0xffffffffu, mid.x, 1);
        if (lane == 0)  f0 = 0.f;
        if (lane == 31) f5 = 0.f;

        // kw = 0 : tap kh*3+0 multiplies window offset [0..3]
        {
            float4 wv4 = ldcs4(pb + (kh * 3 + 0) * HW);
            acc0 = fmaf(wv4.x, f0,    acc0);
            acc1 = fmaf(wv4.y, mid.x, acc1);
            acc2 = fmaf(wv4.z, mid.y, acc2);
            acc3 = fmaf(wv4.w, mid.z, acc3);
        }
        // kw = 1 : offset [1..4]
        {
            float4 wv4 = ldcs4(pb + (kh * 3 + 1) * HW);
            acc0 = fmaf(wv4.x, mid.x, acc0);
            acc1 = fmaf(wv4.y, mid.y, acc1);
            acc2 = fmaf(wv4.z, mid.z, acc2);
            acc3 = fmaf(wv4.w, mid.w, acc3);
        }
        // kw = 2 : offset [2..5]
        {
            float4 wv4 = ldcs4(pb + (kh * 3 + 2) * HW);
            acc0 = fmaf(wv4.x, mid.y, acc0);
            acc1 = fmaf(wv4.y, mid.z, acc1);
            acc2 = fmaf(wv4.z, mid.w, acc2);
            acc3 = fmaf(wv4.w, f5,    acc3);
        }
    }

    float4 o;
    o.x = acc0 >= 0.f ? acc0 : 0.2f * acc0;
    o.y = acc1 >= 0.f ? acc1 : 0.2f * acc1;
    o.z = acc2 >= 0.f ? acc2 : 0.2f * acc2;
    o.w = acc3 >= 0.f ? acc3 : 0.2f * acc3;

    stcs4(out + (size_t)nc * HW + h * W + w0, o);
}

extern "C" void kernel_launch(void* const* d_in, const int* in_sizes, int n_in,
                              void* d_out, int out_size)
{
    const float* feature = (const float*)d_in[0];   // 8*64*128*128
    const float* filters = (const float*)d_in[1];   // 8*576*128*128
    float* out = (float*)d_out;

    // total float4 outputs: 8*64*128*128/4 = 2,097,152
    const int total_vec = 8 * 64 * 128 * (128 / 4);
    const int threads = 256;
    const int blocks = total_vec / threads;         // 8192

    fac_leaky_kernel<<<blocks, threads>>>(feature, filters, out);
}